// round 2
// baseline (speedup 1.0000x reference)
#include <cuda_runtime.h>

// Problem constants
#define Bx   8
#define Cx   256
#define Kx   19
#define HWx  16384
#define HW4  4096      // HW / 4 (float4 units)
#define Sx   4         // hw splits
#define CBx  32        // C / 8  (8 c-rows per block: 2 warps x RC)
#define RC   4         // c-rows per warp (register blocking)

// Scratch (no device allocation allowed -> __device__ globals)
__device__ float g_att_part[Sx * Bx * Cx * Kx];   // [s][b][c][k] partials
__device__ float g_scale[Bx * Cx];                // per-(b,c) gate

// ---------------------------------------------------------------------------
// Kernel 1: partial att[b,c,k] = sum_{hw in split s} feature[b,c,hw]*map[b,k,hw]
// Each warp owns RC=4 consecutive c rows; lanes stride hw in float4 units.
// 76 scalar accumulators per lane; map float4 reused across 4 c rows (16 FMA
// per map load) -> FFMA-pipe bound, not L1-byte bound.
// ---------------------------------------------------------------------------
__global__ __launch_bounds__(64) void k_att(const float* __restrict__ feat,
                                            const float* __restrict__ map) {
    const int bid  = blockIdx.x;
    const int s    = bid % Sx;
    const int cb   = (bid / Sx) % CBx;
    const int b    = bid / (Sx * CBx);
    const int w    = threadIdx.x >> 5;
    const int lane = threadIdx.x & 31;
    const int c0   = cb * 8 + w * RC;

    const float4* __restrict__ f4 = (const float4*)feat;
    const float4* __restrict__ m4 = (const float4*)map;

    float acc[Kx * RC];
    #pragma unroll
    for (int i = 0; i < Kx * RC; i++) acc[i] = 0.f;

    const int   hw4_per_s = HW4 / Sx;                 // 1024 float4 per split
    const int   iters     = hw4_per_s / 32;           // 32
    const int   idx0      = s * hw4_per_s + lane;
    const float4* fbase   = f4 + (size_t)(b * Cx + c0) * HW4;
    const float4* mbase   = m4 + (size_t)(b * Kx) * HW4;

    for (int it = 0; it < iters; it++) {
        const int idx = idx0 + it * 32;
        float4 fv[RC];
        #pragma unroll
        for (int c = 0; c < RC; c++)
            fv[c] = fbase[(size_t)c * HW4 + idx];
        #pragma unroll
        for (int k = 0; k < Kx; k++) {
            const float4 mv = mbase[(size_t)k * HW4 + idx];
            #pragma unroll
            for (int c = 0; c < RC; c++) {
                acc[k * RC + c] += fv[c].x * mv.x;
                acc[k * RC + c] += fv[c].y * mv.y;
                acc[k * RC + c] += fv[c].z * mv.z;
                acc[k * RC + c] += fv[c].w * mv.w;
            }
        }
    }

    // Warp reduction over the 32 hw-lanes for each of the 76 accumulators.
    #pragma unroll
    for (int i = 0; i < Kx * RC; i++) {
        float v = acc[i];
        #pragma unroll
        for (int off = 16; off; off >>= 1)
            v += __shfl_down_sync(0xffffffffu, v, off);
        acc[i] = v;
    }

    if (lane == 0) {
        float* outp = g_att_part + ((size_t)((s * Bx + b) * Cx + c0)) * Kx;
        #pragma unroll
        for (int c = 0; c < RC; c++)
            #pragma unroll
            for (int k = 0; k < Kx; k++)
                outp[c * Kx + k] = acc[k * RC + c];
    }
}

// ---------------------------------------------------------------------------
// Kernel 2: scale[b,c] = sum_k sigmoid(att[b,c,k]) * gamma[k]
// ---------------------------------------------------------------------------
__global__ void k_scale(const float* __restrict__ gamma) {
    const int i = blockIdx.x * blockDim.x + threadIdx.x;   // i = b*C + c
    if (i >= Bx * Cx) return;
    float sc = 0.f;
    #pragma unroll
    for (int k = 0; k < Kx; k++) {
        float a = 0.f;
        #pragma unroll
        for (int s = 0; s < Sx; s++)
            a += g_att_part[((size_t)s * Bx * Cx + i) * Kx + k];
        const float sig = 1.f / (1.f + __expf(-a));
        sc += gamma[k] * sig;
    }
    g_scale[i] = sc;
}

// ---------------------------------------------------------------------------
// Kernel 3: out = feature * (1 + scale[b,c]); pure HBM stream, float4.
// Row index in float4 space = idx >> 12 (HW4 = 4096 = 2^12).
// ---------------------------------------------------------------------------
__global__ __launch_bounds__(256) void k_apply(const float* __restrict__ feat,
                                               float* __restrict__ out) {
    const int i = blockIdx.x * blockDim.x + threadIdx.x;  // float4 index
    const float s = 1.f + g_scale[i >> 12];
    float4 f = ((const float4*)feat)[i];
    f.x *= s; f.y *= s; f.z *= s; f.w *= s;
    ((float4*)out)[i] = f;
}

// ---------------------------------------------------------------------------
extern "C" void kernel_launch(void* const* d_in, const int* in_sizes, int n_in,
                              void* d_out, int out_size) {
    const float* feat  = (const float*)d_in[0];
    const float* map_  = (const float*)d_in[1];
    const float* gamma = (const float*)d_in[2];
    float* out = (float*)d_out;

    k_att  <<<Bx * CBx * Sx, 64>>>(feat, map_);
    k_scale<<<(Bx * Cx + 255) / 256, 256>>>(gamma);
    k_apply<<<(Bx * Cx * HW4) / 256, 256>>>(feat, out);
}

// round 3
// speedup vs baseline: 1.0958x; 1.0958x over previous
#include <cuda_runtime.h>
#include <cstdint>

// Problem constants
#define Bx    8
#define Cx    256
#define Kx    19
#define HW4   4096          // HW / 4 (float4 units), HW = 128*128
#define Sx    8             // hw splits -> grid parallelism
#define RC    4             // c-rows per warp (register blocking)
#define WARPS 4             // warps per block
#define CG    (WARPS*RC)    // 16 c-rows per block
#define NCG   (Cx/CG)       // 16 c-groups
#define CH    32            // float4 columns per smem chunk
#define HW4S  (HW4/Sx)      // 512 float4 per split
#define NCHUNK (HW4S/CH)    // 16 chunks per block

// Scratch (no device allocation allowed -> __device__ globals)
__device__ float g_att_part[Sx * Bx * Cx * Kx];   // [s][b][c][k]
__device__ float g_scale[Bx * Cx];

// ---- cp.async helpers (16B) ------------------------------------------------
__device__ __forceinline__ void cp_async16(uint32_t saddr, const void* gptr) {
    asm volatile("cp.async.cg.shared.global [%0], [%1], 16;\n" :: "r"(saddr), "l"(gptr));
}
__device__ __forceinline__ void cp_commit() {
    asm volatile("cp.async.commit_group;\n");
}
template <int N>
__device__ __forceinline__ void cp_wait() {
    asm volatile("cp.async.wait_group %0;\n" :: "n"(N));
}
__device__ __forceinline__ uint32_t smem_u32(const void* p) {
    return (uint32_t)__cvta_generic_to_shared(p);
}

// ---------------------------------------------------------------------------
// Kernel 1: att partials. Map tile staged in smem (double-buffered cp.async);
// feature streamed via LDG.128 hoisted to chunk top; 76 FFMA accumulators.
// ---------------------------------------------------------------------------
__global__ __launch_bounds__(128, 4)
void k_att(const float* __restrict__ feat, const float* __restrict__ map) {
    __shared__ float4 smap[2][Kx * CH];           // 2 x 9728 B

    const int bid  = blockIdx.x;
    const int s    = bid % Sx;
    const int cg   = (bid / Sx) % NCG;
    const int b    = bid / (Sx * NCG);
    const int tid  = threadIdx.x;
    const int w    = tid >> 5;
    const int lane = tid & 31;
    const int c0   = cg * CG + w * RC;
    const int hw0  = s * HW4S;

    const float4* __restrict__ f4 = (const float4*)feat;
    const float4* __restrict__ m4 = (const float4*)map;

    const float4* fbase = f4 + (size_t)(b * Cx + c0) * HW4 + hw0;
    const float4* mbase = m4 + (size_t)(b * Kx) * HW4 + hw0;

    float acc[Kx * RC];
    #pragma unroll
    for (int i = 0; i < Kx * RC; i++) acc[i] = 0.f;

    // ---- map-chunk loader: 19*32 = 608 float4 by 128 threads ----
    auto load_map_chunk = [&](int buf, int chunk) {
        const float4* src = mbase + chunk * CH;
        uint32_t sb = smem_u32(&smap[buf][0]);
        #pragma unroll
        for (int j = 0; j < 4; j++) {
            int e = tid + j * 128;                 // e = k*CH + col
            int k = e >> 5, col = e & 31;
            cp_async16(sb + e * 16, src + (size_t)k * HW4 + col);
        }
        if (tid < Kx * CH - 512) {                 // last 96
            int e = tid + 512;
            int k = e >> 5, col = e & 31;
            cp_async16(sb + e * 16, src + (size_t)k * HW4 + col);
        }
    };

    load_map_chunk(0, 0);
    cp_commit();

    #pragma unroll 1
    for (int ch = 0; ch < NCHUNK; ch++) {
        if (ch + 1 < NCHUNK) { load_map_chunk((ch + 1) & 1, ch + 1); cp_commit(); }

        // Feature loads for this chunk: issued early, covered by smem wait +
        // the FFMA burst of the first k iterations.
        const int col = ch * CH + lane;
        float4 fv[RC];
        #pragma unroll
        for (int c = 0; c < RC; c++)
            fv[c] = fbase[(size_t)c * HW4 + col];

        if (ch + 1 < NCHUNK) cp_wait<1>(); else cp_wait<0>();
        __syncthreads();

        const float4* sb = smap[ch & 1];
        #pragma unroll
        for (int k = 0; k < Kx; k++) {
            const float4 mv = sb[k * CH + lane];
            #pragma unroll
            for (int c = 0; c < RC; c++) {
                acc[k * RC + c] += fv[c].x * mv.x;
                acc[k * RC + c] += fv[c].y * mv.y;
                acc[k * RC + c] += fv[c].z * mv.z;
                acc[k * RC + c] += fv[c].w * mv.w;
            }
        }
        __syncthreads();   // protect smem buffer before next cp.async overwrite
    }

    // Warp reduction over 32 hw-lanes for each of the 76 accumulators.
    #pragma unroll
    for (int i = 0; i < Kx * RC; i++) {
        float v = acc[i];
        #pragma unroll
        for (int off = 16; off; off >>= 1)
            v += __shfl_down_sync(0xffffffffu, v, off);
        acc[i] = v;
    }

    if (lane == 0) {
        float* outp = g_att_part + ((size_t)((s * Bx + b) * Cx + c0)) * Kx;
        #pragma unroll
        for (int c = 0; c < RC; c++)
            #pragma unroll
            for (int k = 0; k < Kx; k++)
                outp[c * Kx + k] = acc[k * RC + c];
    }
}

// ---------------------------------------------------------------------------
// Kernel 2: scale[b,c] = sum_k sigmoid(att[b,c,k]) * gamma[k]
// ---------------------------------------------------------------------------
__global__ void k_scale(const float* __restrict__ gamma) {
    const int i = blockIdx.x * blockDim.x + threadIdx.x;   // i = b*C + c
    if (i >= Bx * Cx) return;
    float sc = 0.f;
    #pragma unroll
    for (int k = 0; k < Kx; k++) {
        float a = 0.f;
        #pragma unroll
        for (int s = 0; s < Sx; s++)
            a += g_att_part[((size_t)s * Bx * Cx + i) * Kx + k];
        const float sig = 1.f / (1.f + __expf(-a));
        sc += gamma[k] * sig;
    }
    g_scale[i] = sc;
}

// ---------------------------------------------------------------------------
// Kernel 3: out = feature * (1 + scale[b,c]); pure HBM stream, float4.
// ---------------------------------------------------------------------------
__global__ __launch_bounds__(256)
void k_apply(const float* __restrict__ feat, float* __restrict__ out) {
    const int i = blockIdx.x * blockDim.x + threadIdx.x;  // float4 index
    const float s = 1.f + g_scale[i >> 12];               // HW4 = 4096 = 2^12
    float4 f = ((const float4*)feat)[i];
    f.x *= s; f.y *= s; f.z *= s; f.w *= s;
    ((float4*)out)[i] = f;
}

// ---------------------------------------------------------------------------
extern "C" void kernel_launch(void* const* d_in, const int* in_sizes, int n_in,
                              void* d_out, int out_size) {
    const float* feat  = (const float*)d_in[0];
    const float* map_  = (const float*)d_in[1];
    const float* gamma = (const float*)d_in[2];
    float* out = (float*)d_out;

    k_att  <<<Bx * NCG * Sx, 128>>>(feat, map_);
    k_scale<<<(Bx * Cx + 255) / 256, 256>>>(gamma);
    k_apply<<<(Bx * Cx * HW4) / 256, 256>>>(feat, out);
}

// round 5
// speedup vs baseline: 1.1615x; 1.0600x over previous
#include <cuda_runtime.h>
#include <cstdint>

// Problem constants
#define Bx    8
#define Cx    256
#define Kx    19
#define HW4   4096          // HW / 4 (float4 units), HW = 128*128
#define RC    4             // c-rows per warp
#define WARPS 4
#define CG    (WARPS*RC)    // 16 c-rows per block
#define NCG   (Cx/CG)       // 16
#define CH    32            // float4 columns per smem chunk
#define NCHT  (HW4/CH)      // 128 chunks per (b,cgroup)
#define Sx    7             // hw splits -> grid 896 ~ 3 waves @ 2 blk/SM

// Scratch (__device__ globals; no allocation allowed)
// att quarter-partials: [s][b][c][k][quarter(4)]
__device__ float g_att_part[Sx * Bx * Cx * Kx * 4];

// ---- cp.async helpers ------------------------------------------------------
__device__ __forceinline__ void cp_async16(uint32_t saddr, const void* gptr) {
    asm volatile("cp.async.cg.shared.global [%0], [%1], 16;\n" :: "r"(saddr), "l"(gptr));
}
__device__ __forceinline__ void cp_commit() {
    asm volatile("cp.async.commit_group;\n");
}
template <int N>
__device__ __forceinline__ void cp_wait() {
    asm volatile("cp.async.wait_group %0;\n" :: "n"(N));
}
__device__ __forceinline__ uint32_t smem_u32(const void* p) {
    return (uint32_t)__cvta_generic_to_shared(p);
}

// Packed dual-FMA: acc(f32x2) += a(f32x2) * b(f32x2)   [Blackwell FFMA2]
__device__ __forceinline__ void ffma2(unsigned long long& acc,
                                      unsigned long long a, unsigned long long b) {
    asm("fma.rn.f32x2 %0, %1, %2, %0;" : "+l"(acc) : "l"(a), "l"(b));
}

// ---------------------------------------------------------------------------
// Kernel 1: att partials. Map chunks staged via double-buffered cp.async;
// feature register-prefetched one chunk ahead; packed f32x2 accumulators:
// acc2[k][c].lo collects x,z terms; .hi collects y,w; collapsed at the end.
// Buffer parity invariant: buffer index == (global chunk index) & 1, INCLUDING
// the initial load (ch_beg may be odd for some splits).
// ---------------------------------------------------------------------------
__global__ __launch_bounds__(128)
void k_att(const float* __restrict__ feat, const float* __restrict__ map) {
    __shared__ float4 smap[2][Kx * CH];            // 2 x 9728 B

    const int bid  = blockIdx.x;
    const int s    = bid % Sx;
    const int cg   = (bid / Sx) % NCG;
    const int b    = bid / (Sx * NCG);
    const int tid  = threadIdx.x;
    const int w    = tid >> 5;
    const int lane = tid & 31;
    const int c0   = cg * CG + w * RC;

    const int ch_beg = (s * NCHT) / Sx;            // variable 18/19-chunk ranges
    const int ch_end = ((s + 1) * NCHT) / Sx;

    const float4* __restrict__ f4 = (const float4*)feat;
    const float4* __restrict__ m4 = (const float4*)map;
    const float4* fbase = f4 + (size_t)(b * Cx + c0) * HW4;
    const float4* mbase = m4 + (size_t)(b * Kx) * HW4;

    unsigned long long acc2[Kx * RC];
    #pragma unroll
    for (int i = 0; i < Kx * RC; i++) acc2[i] = 0ull;

    // map-chunk loader: 19*32 = 608 float4 by 128 threads
    auto load_map_chunk = [&](int buf, int chunk) {
        const float4* src = mbase + chunk * CH;
        uint32_t sb = smem_u32(&smap[buf][0]);
        #pragma unroll
        for (int j = 0; j < 4; j++) {
            int e = tid + j * 128;                 // e = k*CH + col
            cp_async16(sb + e * 16, src + (size_t)(e >> 5) * HW4 + (e & 31));
        }
        if (tid < Kx * CH - 512) {
            int e = tid + 512;
            cp_async16(sb + e * 16, src + (size_t)(e >> 5) * HW4 + (e & 31));
        }
    };
    // feature loads for one chunk (packed pairs, free from float4 alignment)
    auto load_feat = [&](int chunk, unsigned long long fxy[RC], unsigned long long fzw[RC]) {
        const int col = chunk * CH + lane;
        #pragma unroll
        for (int c = 0; c < RC; c++) {
            ulonglong2 v = *(const ulonglong2*)(fbase + (size_t)c * HW4 + col);
            fxy[c] = v.x; fzw[c] = v.y;
        }
    };

    unsigned long long fxy[RC], fzw[RC], nxy[RC], nzw[RC];

    load_map_chunk(ch_beg & 1, ch_beg);            // <-- parity fix (was buf 0)
    cp_commit();
    load_feat(ch_beg, fxy, fzw);

    #pragma unroll 1
    for (int ch = ch_beg; ch < ch_end; ch++) {
        const bool more = (ch + 1 < ch_end);
        if (more) { load_map_chunk((ch + 1) & 1, ch + 1); cp_commit(); }
        if (more) cp_wait<1>(); else cp_wait<0>();
        __syncthreads();
        if (more) load_feat(ch + 1, nxy, nzw);     // LDG covered by this chunk's FFMA2

        const float4* sb = smap[ch & 1];
        #pragma unroll
        for (int k = 0; k < Kx; k++) {
            ulonglong2 mv = *(const ulonglong2*)(&sb[k * CH + lane]);
            #pragma unroll
            for (int c = 0; c < RC; c++) {
                ffma2(acc2[k * RC + c], fxy[c], mv.x);
                ffma2(acc2[k * RC + c], fzw[c], mv.y);
            }
        }
        __syncthreads();                           // protect smem before overwrite
        #pragma unroll
        for (int c = 0; c < RC; c++) { fxy[c] = nxy[c]; fzw[c] = nzw[c]; }
    }

    // Collapse packed pairs and 3-round lane reduction -> quarter partials.
    #pragma unroll
    for (int i = 0; i < Kx * RC; i++) {
        float lo = __uint_as_float((uint32_t)acc2[i]);
        float hi = __uint_as_float((uint32_t)(acc2[i] >> 32));
        float v = lo + hi;
        v += __shfl_down_sync(0xffffffffu, v, 16);
        v += __shfl_down_sync(0xffffffffu, v, 8);
        v += __shfl_down_sync(0xffffffffu, v, 4);
        acc2[i] = (unsigned long long)__float_as_uint(v);   // reuse storage
    }

    if (lane < 4) {
        #pragma unroll
        for (int c = 0; c < RC; c++)
            #pragma unroll
            for (int k = 0; k < Kx; k++) {
                float v = __uint_as_float((uint32_t)acc2[k * RC + c]);
                g_att_part[((((size_t)s * Bx + b) * Cx + (c0 + c)) * Kx + k) * 4 + lane] = v;
            }
    }
}

// ---------------------------------------------------------------------------
// Kernel 2 (fused scale+apply): one block per (b,c) row.
// scale = sum_k gamma[k]*sigmoid(sum_{s,q} part); then stream out = f*(1+scale).
// ---------------------------------------------------------------------------
__global__ __launch_bounds__(256)
void k_apply(const float* __restrict__ feat, const float* __restrict__ gamma,
             float* __restrict__ out) {
    __shared__ float sh[Kx + 1];
    const int row = blockIdx.x;                    // b*Cx + c
    const int tid = threadIdx.x;

    if (tid < Kx) {
        const float* p = g_att_part + (size_t)row * Kx * 4 + tid * 4;
        float a = 0.f;
        #pragma unroll
        for (int s = 0; s < Sx; s++) {
            const float* ps = p + (size_t)s * Bx * Cx * Kx * 4;
            a += ps[0] + ps[1] + ps[2] + ps[3];
        }
        sh[tid] = gamma[tid] * (1.f / (1.f + __expf(-a)));
    }
    __syncthreads();
    if (tid == 0) {
        float sc = 0.f;
        #pragma unroll
        for (int k = 0; k < Kx; k++) sc += sh[k];
        sh[Kx] = 1.f + sc;
    }
    __syncthreads();
    const float s = sh[Kx];

    const float4* __restrict__ fr = (const float4*)feat + (size_t)row * HW4;
    float4* __restrict__ orow = (float4*)out + (size_t)row * HW4;
    #pragma unroll 4
    for (int i = tid; i < HW4; i += 256) {
        float4 f = fr[i];
        f.x *= s; f.y *= s; f.z *= s; f.w *= s;
        orow[i] = f;
    }
}

// ---------------------------------------------------------------------------
extern "C" void kernel_launch(void* const* d_in, const int* in_sizes, int n_in,
                              void* d_out, int out_size) {
    const float* feat  = (const float*)d_in[0];
    const float* map_  = (const float*)d_in[1];
    const float* gamma = (const float*)d_in[2];
    float* out = (float*)d_out;

    k_att  <<<Bx * NCG * Sx, 128>>>(feat, map_);
    k_apply<<<Bx * Cx, 256>>>(feat, gamma, out);
}